// round 1
// baseline (speedup 1.0000x reference)
#include <cuda_runtime.h>
#include <math.h>

#define NB 4
#define NT 1024
#define NCH 4
#define NF 481
#define NK 48
#define NPV 16
#define DT_MS 10.0f
#define MAIN_THREADS 192

// ---------- device scratch (static, no allocation) ----------
__device__ float4 g_band4[(NF * NK) / 2];          // interleaved (br,bi) pairs, 2 complex per float4
__device__ float  g_ds[NK];                        // per-band normalizer  max(sum_f band_real, 1e-20)
__device__ float  g_pvx[NB * NT * NK * NPV];       // pre-IIR power vectors, 12.6 MB

// ---------- f32x2 packed-FMA helpers ----------
__device__ __forceinline__ unsigned long long pk2(float x, float y) {
    unsigned long long r;
    asm("mov.b64 %0, {%1, %2};" : "=l"(r) : "f"(x), "f"(y));
    return r;
}
__device__ __forceinline__ void fma2(unsigned long long& c, unsigned long long a, unsigned long long b) {
    asm("fma.rn.f32x2 %0, %1, %2, %0;" : "+l"(c) : "l"(a), "l"(b));
}
__device__ __forceinline__ float2 upk2(unsigned long long v) {
    float2 r;
    asm("mov.b64 {%0, %1}, %2;" : "=f"(r.x), "=f"(r.y) : "l"(v));
    return r;
}

// ---------- prep: interleave band into (re,im) pairs ----------
__global__ void prep_band_kernel(const float* __restrict__ br, const float* __restrict__ bi) {
    int i = blockIdx.x * blockDim.x + threadIdx.x;
    if (i < NF * NK) {
        ((float2*)g_band4)[i] = make_float2(br[i], bi[i]);
    }
}

// ---------- prep: ds[k] = max(sum_f band_real[f,k], 1e-20) ----------
__global__ void prep_ds_kernel(const float* __restrict__ br) {
    __shared__ float red[64];
    int k = blockIdx.x, tx = threadIdx.x;
    float s = 0.f;
    for (int f = tx; f < NF; f += 64) s += br[f * NK + k];
    red[tx] = s;
    __syncthreads();
    for (int off = 32; off > 0; off >>= 1) {
        if (tx < off) red[tx] += red[tx + off];
        __syncthreads();
    }
    if (tx == 0) g_ds[k] = fmaxf(red[0], 1e-20f);
}

// ---------- main: one block per (b,t) ----------
// smem layout (floats):
//   [0,      16*NF)  sCov : {d0..d3, (ur,ui) x 6 pairs}[f]  component-major, stride NF
//   [16*NF,  32*NF)  sA   : multiplier streams {d0..d3, ar0..ar5, ai0..ai5}[f]
//   [32*NF,  32*NF+512) sM : real 16x32 projection  [p][2c]=Re(c2pv), [p][2c+1]=-Im(c2pv)
//   after the GEMM phase, sCov region is reused:
//   [0, 1536) as float2 sAcc[k][stream], [2048, 3584) sBC[k][32] interleaved bc
__global__ __launch_bounds__(MAIN_THREADS)
void pv_main_kernel(const float* __restrict__ bins_real,
                    const float* __restrict__ bins_imag,
                    const float* __restrict__ c2pv_real,
                    const float* __restrict__ c2pv_imag) {
    extern __shared__ float smem[];
    float*  sCov = smem;
    float*  sA   = smem + 16 * NF;
    float*  sM   = smem + 32 * NF;
    float2* sAcc = (float2*)smem;
    float*  sBC  = smem + 2048;

    const int tid = threadIdx.x;
    const int bt  = blockIdx.x;
    const int b   = bt >> 10;
    const int t   = bt & (NT - 1);

    // load projection matrix: pv[p] = sum_c Re(c2pv[p,c]) * bc_re[c] - Im(c2pv[p,c]) * bc_im[c]
    for (int i = tid; i < NPV * 32; i += MAIN_THREADS) {
        int p = i >> 5, r = i & 31, c = r >> 1;
        sM[i] = (r & 1) ? -c2pv_imag[p * 16 + c] : c2pv_real[p * 16 + c];
    }

    // ---- pass 1: trace-normalized covariance per bin ----
    const long base = ((long)(b * NT + t)) * NCH * NF;
    for (int f = tid; f < NF; f += MAIN_THREADS) {
        float xr[NCH], xi[NCH];
        #pragma unroll
        for (int ch = 0; ch < NCH; ch++) {
            xr[ch] = bins_real[base + ch * NF + f];
            xi[ch] = bins_imag[base + ch * NF + f];
        }
        float d[NCH];
        float pw = 0.f;
        #pragma unroll
        for (int i = 0; i < NCH; i++) {
            d[i] = xr[i] * xr[i] + xi[i] * xi[i];
            pw += d[i];
        }
        float inv = 1.0f / fmaxf(pw, 1e-20f);
        #pragma unroll
        for (int i = 0; i < NCH; i++) sCov[i * NF + f] = d[i] * inv;
        int m = 0;
        #pragma unroll
        for (int i = 0; i < NCH; i++) {
            #pragma unroll
            for (int j = i + 1; j < NCH; j++) {
                // cov_ij = x_i * conj(x_j)
                float ur = xr[i] * xr[j] + xi[i] * xi[j];
                float ui = xi[i] * xr[j] - xr[i] * xi[j];
                sCov[(4 + 2 * m) * NF + f] = ur * inv;
                sCov[(5 + 2 * m) * NF + f] = ui * inv;
                m++;
            }
        }
    }
    __syncthreads();

    // ---- pass 2: phase adjust  adj = |cov_f| * z/|z|,  z = conj(cov_lo)*cov_hi ----
    for (int f = tid; f < NF; f += MAIN_THREADS) {
        int lo = f - 1;
        if (lo < 0) lo = 0;
        if (lo > NF - 3) lo = NF - 3;
        int hi = lo + 2;
        #pragma unroll
        for (int i = 0; i < 4; i++) sA[i * NF + f] = sCov[i * NF + f];
        #pragma unroll
        for (int m = 0; m < 6; m++) {
            float ur = sCov[(4 + 2 * m) * NF + f];
            float uv = sCov[(5 + 2 * m) * NF + f];
            float lr = sCov[(4 + 2 * m) * NF + lo];
            float li = sCov[(5 + 2 * m) * NF + lo];
            float hr = sCov[(4 + 2 * m) * NF + hi];
            float hv = sCov[(5 + 2 * m) * NF + hi];
            float zr = lr * hr + li * hv;
            float zi = lr * hv - li * hr;
            float mag = sqrtf(ur * ur + uv * uv);
            float zn = zr * zr + zi * zi;
            float ar, ai;
            if (zn > 0.0f) {
                float s = mag * rsqrtf(zn);
                ar = zr * s;
                ai = zi * s;
            } else {  // angle(0) = 0 -> unit phase
                ar = mag;
                ai = 0.0f;
            }
            sA[(4 + m) * NF + f]  = ar;   // P-stream multiplier (Re adj)
            sA[(10 + m) * NF + f] = ai;   // Q-stream multiplier (Im adj)
        }
    }
    __syncthreads();

    // ---- pass 3: contraction  acc[k,stream] += a[stream,f] * band[f,k]  (f32x2 packed) ----
    const int cp = tid & 15;   // stream: 0..3 diag, 4..9 P, 10..15 Q
    const int kg = tid >> 4;   // 0..11, each handles 4 consecutive k
    unsigned long long A0 = 0, A1 = 0, A2 = 0, A3 = 0;
    const float* aptr = sA + cp * NF;
    const float4* bptr = g_band4 + kg * 2;
    #pragma unroll 4
    for (int f = 0; f < NF; f++) {
        float a = aptr[f];
        float4 b01 = bptr[f * 24];
        float4 b23 = bptr[f * 24 + 1];
        unsigned long long Av = pk2(a, a);
        fma2(A0, Av, pk2(b01.x, b01.y));
        fma2(A1, Av, pk2(b01.z, b01.w));
        fma2(A2, Av, pk2(b23.x, b23.y));
        fma2(A3, Av, pk2(b23.z, b23.w));
    }
    // stash accumulators (sCov region is dead now; sA still live for other threads, untouched)
    {
        int k0 = kg * 4;
        sAcc[(k0 + 0) * 16 + cp] = upk2(A0);
        sAcc[(k0 + 1) * 16 + cp] = upk2(A1);
        sAcc[(k0 + 2) * 16 + cp] = upk2(A2);
        sAcc[(k0 + 3) * 16 + cp] = upk2(A3);
    }
    __syncthreads();

    // ---- pass 4: reconstruct full Hermitian bc[k][16 complex] ----
    if (tid < NK) {
        const int pi[6] = {0, 0, 0, 1, 1, 2};
        const int pj[6] = {1, 2, 3, 2, 3, 3};
        const float2* row = sAcc + tid * 16;
        float* bc = sBC + tid * 32;
        #pragma unroll
        for (int i = 0; i < 4; i++) {
            float2 D = row[i];
            bc[(i * 4 + i) * 2]     = D.x;
            bc[(i * 4 + i) * 2 + 1] = D.y;
        }
        #pragma unroll
        for (int m = 0; m < 6; m++) {
            float2 Pm = row[4 + m];
            float2 Qm = row[10 + m];
            int cij = pi[m] * 4 + pj[m];
            int cji = pj[m] * 4 + pi[m];
            bc[cij * 2]     = Pm.x - Qm.y;   // bc_ij = P + i*Q
            bc[cij * 2 + 1] = Pm.y + Qm.x;
            bc[cji * 2]     = Pm.x + Qm.y;   // bc_ji = P - i*Q
            bc[cji * 2 + 1] = Pm.y - Qm.x;
        }
    }
    __syncthreads();

    // ---- pass 5: pvx[k,p] = Re(c2pv . bc) / ds[k] ----
    float* outBase = g_pvx + ((long)(b * NT + t)) * NK * NPV;
    for (int idx = tid; idx < NK * NPV; idx += MAIN_THREADS) {
        int k = idx >> 4, p = idx & 15;
        const float* mrow = sM + p * 32;
        const float* brow = sBC + k * 32;
        float s = 0.f;
        #pragma unroll
        for (int r = 0; r < 32; r++) s = fmaf(mrow[r], brow[r], s);
        outBase[idx] = s / g_ds[k];
    }
}

// ---------- IIR over frames + transpose to (B,K,T,P) ----------
__global__ void iir_kernel(const float* __restrict__ tau, float* __restrict__ out) {
    int g = blockIdx.x * blockDim.x + threadIdx.x;
    if (g >= NB * NK * NPV) return;
    int p = g & 15;
    int k = (g >> 4) % NK;
    int b = g / (NK * NPV);
    float alpha = expf(-DT_MS / tau[k]);
    float beta = 1.0f - alpha;
    const float* src = g_pvx + (((long)b * NT) * NK + k) * NPV + p;
    float* dst = out + (((long)(b * NK + k)) * NT) * NPV + p;
    float y = src[0];
    dst[0] = y;
    #pragma unroll 4
    for (int t = 1; t < NT; t++) {
        float x = src[(long)t * NK * NPV];
        y = alpha * y + beta * x;
        dst[(long)t * NPV] = y;
    }
}

extern "C" void kernel_launch(void* const* d_in, const int* in_sizes, int n_in,
                              void* d_out, int out_size) {
    const float* bins_real = (const float*)d_in[0];
    const float* bins_imag = (const float*)d_in[1];
    const float* band_real = (const float*)d_in[2];
    const float* band_imag = (const float*)d_in[3];
    const float* c2pv_real = (const float*)d_in[4];
    const float* c2pv_imag = (const float*)d_in[5];
    const float* tau       = (const float*)d_in[6];
    float* out = (float*)d_out;

    const int smem_bytes = (32 * NF + 512) * (int)sizeof(float);  // 63,616 B
    cudaFuncSetAttribute((const void*)pv_main_kernel,
                         cudaFuncAttributeMaxDynamicSharedMemorySize, smem_bytes);

    prep_band_kernel<<<(NF * NK + 255) / 256, 256>>>(band_real, band_imag);
    prep_ds_kernel<<<NK, 64>>>(band_real);
    pv_main_kernel<<<NB * NT, MAIN_THREADS, smem_bytes>>>(bins_real, bins_imag,
                                                          c2pv_real, c2pv_imag);
    iir_kernel<<<(NB * NK * NPV + 255) / 256, 256>>>(tau, out);
}